// round 1
// baseline (speedup 1.0000x reference)
#include <cuda_runtime.h>

#define N_NODES 500000
#define E_EDGES 16000000
#define NVEC    (E_EDGES / 4)

// Scratch (allocation-free rule: __device__ globals)
__device__ float g_dsrc[N_NODES];   // out-degree accumulator -> out_deg^-0.5
__device__ float g_ddst[N_NODES];   // in-degree accumulator  -> in_deg^-0.5
__device__ float g_xs[N_NODES];     // per-node scalar message for scatter pass 1 (y * d_src)
__device__ float g_x2[N_NODES];     // per-node scalar message for scatter pass 2
__device__ float g_agg[N_NODES];    // scatter target pass 1
__device__ float g_agg2[N_NODES];   // scatter target pass 2

// ---------------------------------------------------------------------------
// Node-level kernels
// ---------------------------------------------------------------------------

__global__ void zero_deg_kernel() {
    int i = blockIdx.x * blockDim.x + threadIdx.x;
    if (i < N_NODES) { g_dsrc[i] = 0.0f; g_ddst[i] = 0.0f; }
}

__global__ void deg_kernel(const int4* __restrict__ src4, const int4* __restrict__ dst4) {
    int i = blockIdx.x * blockDim.x + threadIdx.x;
    if (i >= NVEC) return;
    int4 s = __ldg(src4 + i);
    int4 d = __ldg(dst4 + i);
    atomicAdd(&g_dsrc[s.x], 1.0f);
    atomicAdd(&g_dsrc[s.y], 1.0f);
    atomicAdd(&g_dsrc[s.z], 1.0f);
    atomicAdd(&g_dsrc[s.w], 1.0f);
    atomicAdd(&g_ddst[d.x], 1.0f);
    atomicAdd(&g_ddst[d.y], 1.0f);
    atomicAdd(&g_ddst[d.z], 1.0f);
    atomicAdd(&g_ddst[d.w], 1.0f);
}

// deg -> norm, y sign fix, first xs, zero agg
__global__ void init_kernel(const float* __restrict__ y_in, float* __restrict__ y) {
    int i = blockIdx.x * blockDim.x + threadIdx.x;
    if (i >= N_NODES) return;
    float ds = rsqrtf(fmaxf(g_dsrc[i], 1.0f));
    float dd = rsqrtf(fmaxf(g_ddst[i], 1.0f));
    g_dsrc[i] = ds;
    g_ddst[i] = dd;
    float yv = y_in[i];
    yv = (yv == 0.0f) ? -1.0f : yv;
    y[i]      = yv;
    g_xs[i]   = yv * ds;
    g_agg[i]  = 0.0f;
}

// Full fused layer-1 (fc + resid + LN + PReLU) + layer-2 fc per node.
// Consumes g_agg (scalar), produces g_x2 (scalar). Zeroes g_agg2 for next scatter.
__global__ void node1_kernel(const float* __restrict__ y,
                             const float* __restrict__ W1,  const float* __restrict__ b1,
                             const float* __restrict__ Wres,
                             const float* __restrict__ lng, const float* __restrict__ lnb,
                             const float* __restrict__ pa,
                             const float* __restrict__ W2,  const float* __restrict__ b2) {
    int i = blockIdx.x * blockDim.x + threadIdx.x;
    if (i >= N_NODES) return;
    float a  = g_agg[i];
    float yv = y[i];
    float ds = g_dsrc[i];
    float dd = g_ddst[i];

    float r[8];
    float mu = 0.0f;
#pragma unroll
    for (int k = 0; k < 8; k++) {
        r[k] = (a * __ldg(W1 + k) + __ldg(b1 + k)) * dd + yv * __ldg(Wres + k);
        mu += r[k];
    }
    mu *= 0.125f;
    float var = 0.0f;
#pragma unroll
    for (int k = 0; k < 8; k++) { float t = r[k] - mu; var += t * t; }
    var *= 0.125f;
    float inv   = rsqrtf(var + 1e-5f);
    float alpha = __ldg(pa);

    float dot = 0.0f;
#pragma unroll
    for (int k = 0; k < 8; k++) {
        float t = (r[k] - mu) * inv * __ldg(lng + k) + __ldg(lnb + k);
        t = (t >= 0.0f) ? t : alpha * t;
        dot += t * __ldg(W2 + k);
    }
    g_x2[i]   = ds * dot + __ldg(b2);
    g_agg2[i] = 0.0f;
}

// y += agg2 * d_dst; prepare xs for next loop; zero agg for next scatter1.
__global__ void node2_kernel(float* __restrict__ y) {
    int i = blockIdx.x * blockDim.x + threadIdx.x;
    if (i >= N_NODES) return;
    float yv = y[i] + g_agg2[i] * g_ddst[i];
    y[i]     = yv;
    g_xs[i]  = yv * g_dsrc[i];
    g_agg[i] = 0.0f;
}

// ---------------------------------------------------------------------------
// Edge scatter kernels (the heavy passes): agg[dst] += vals[src]
// ---------------------------------------------------------------------------

__global__ void scatter1_kernel(const int4* __restrict__ src4, const int4* __restrict__ dst4) {
    int i = blockIdx.x * blockDim.x + threadIdx.x;
    if (i >= NVEC) return;
    int4 s = __ldg(src4 + i);
    int4 d = __ldg(dst4 + i);
    float v0 = __ldg(g_xs + s.x);
    float v1 = __ldg(g_xs + s.y);
    float v2 = __ldg(g_xs + s.z);
    float v3 = __ldg(g_xs + s.w);
    atomicAdd(&g_agg[d.x], v0);
    atomicAdd(&g_agg[d.y], v1);
    atomicAdd(&g_agg[d.z], v2);
    atomicAdd(&g_agg[d.w], v3);
}

__global__ void scatter2_kernel(const int4* __restrict__ src4, const int4* __restrict__ dst4) {
    int i = blockIdx.x * blockDim.x + threadIdx.x;
    if (i >= NVEC) return;
    int4 s = __ldg(src4 + i);
    int4 d = __ldg(dst4 + i);
    float v0 = __ldg(g_x2 + s.x);
    float v1 = __ldg(g_x2 + s.y);
    float v2 = __ldg(g_x2 + s.z);
    float v3 = __ldg(g_x2 + s.w);
    atomicAdd(&g_agg2[d.x], v0);
    atomicAdd(&g_agg2[d.y], v1);
    atomicAdd(&g_agg2[d.z], v2);
    atomicAdd(&g_agg2[d.w], v3);
}

// ---------------------------------------------------------------------------
// Launch
// ---------------------------------------------------------------------------

extern "C" void kernel_launch(void* const* d_in, const int* in_sizes, int n_in,
                              void* d_out, int out_size) {
    const float* y_in  = (const float*)d_in[0];
    const int4*  src4  = (const int4*)d_in[1];
    const int4*  dst4  = (const int4*)d_in[2];
    const float* W1    = (const float*)d_in[3];
    const float* b1    = (const float*)d_in[4];
    const float* Wres  = (const float*)d_in[5];
    const float* lng   = (const float*)d_in[6];
    const float* lnb   = (const float*)d_in[7];
    const float* pa    = (const float*)d_in[8];
    const float* W2    = (const float*)d_in[9];
    const float* b2    = (const float*)d_in[10];
    float* y = (float*)d_out;   // working y buffer == output buffer

    const int TB = 256;
    int nb_n = (N_NODES + TB - 1) / TB;
    int nb_e = (NVEC + TB - 1) / TB;

    zero_deg_kernel<<<nb_n, TB>>>();
    deg_kernel<<<nb_e, TB>>>(src4, dst4);
    init_kernel<<<nb_n, TB>>>(y_in, y);

    for (int l = 0; l < 4; l++) {
        scatter1_kernel<<<nb_e, TB>>>(src4, dst4);
        node1_kernel<<<nb_n, TB>>>(y, W1, b1, Wres, lng, lnb, pa, W2, b2);
        scatter2_kernel<<<nb_e, TB>>>(src4, dst4);
        node2_kernel<<<nb_n, TB>>>(y);
    }
}